// round 14
// baseline (speedup 1.0000x reference)
#include <cuda_runtime.h>
#include <cuda_fp16.h>

#define N_ROWS 32768
#define C_DIM  512
#define NE     8192
#define HW     4096
#define BETA_F 0.25f

// GEMM tiling: CTA 128x128, warp 64x32, K-chunks of 128 (fp16)
#define MT 128
#define NT 128
#define KC 128
#define NCHUNK (C_DIM / KC)     // 4
#define NBLK   (NE / NT)        // 64
#define MBLK   (N_ROWS / MT)    // 256
#define ROWB   256u             // smem bytes per tile row (KC fp16)

#define TILE_BYTES  32768u
#define STAGE_BYTES 65536u
#define SMEM_TOTAL  196608      // 3 stages

#define CAP 512
#define INV4096 2.44140625e-4f  // 2^-12, exact

// ---------------- device scratch ----------------
__device__ float g_zz[N_ROWS];
__device__ float g_eps[N_ROWS];
__device__ float g_ee[NE];
__device__ unsigned g_amin[N_ROWS];
__device__ unsigned g_cnt[N_ROWS];
__device__ unsigned long long g_cand[(size_t)N_ROWS * CAP];
__device__ float g_wpart[N_ROWS / 256];
__device__ float g_sumsq;
__device__ __half g_Ah[(size_t)N_ROWS * C_DIM];
__device__ __half g_Bh[(size_t)NE * C_DIM];          // codebook * 2^13
__device__ float g_zt[(size_t)N_ROWS * C_DIM];

// ---------------- helpers ----------------
__device__ __forceinline__ void cpa16(unsigned dst, const void* src) {
    asm volatile("cp.async.cg.shared.global [%0], [%1], 16;" :: "r"(dst), "l"(src));
}
__device__ __forceinline__ void ldsm4(unsigned &r0, unsigned &r1, unsigned &r2,
                                      unsigned &r3, unsigned addr) {
    asm volatile("ldmatrix.sync.aligned.m8n8.x4.shared.b16 {%0,%1,%2,%3},[%4];"
                 : "=r"(r0), "=r"(r1), "=r"(r2), "=r"(r3) : "r"(addr));
}
#define MMA_F16(d, a, b) \
    asm volatile("mma.sync.aligned.m16n8k16.row.col.f32.f16.f16.f32 " \
        "{%0,%1,%2,%3},{%4,%5,%6,%7},{%8,%9},{%0,%1,%2,%3};" \
        : "+f"((d)[0]), "+f"((d)[1]), "+f"((d)[2]), "+f"((d)[3]) \
        : "r"((a)[0]), "r"((a)[1]), "r"((a)[2]), "r"((a)[3]), \
          "r"((b)[0]), "r"((b)[1]))

__device__ __forceinline__ unsigned msk(float s) {
    unsigned b = __float_as_uint(s);
    return b ^ ((b & 0x80000000u) ? 0xFFFFFFFFu : 0x80000000u);
}
__device__ __forceinline__ float msk_inv(unsigned v) {
    return (v & 0x80000000u) ? __uint_as_float(v ^ 0x80000000u)
                             : __uint_as_float(~v);
}

// ---------------- prep: zz, eps, init, mask partials ----------------
__global__ void vq_prep_kernel(const float* __restrict__ z,
                               const float* __restrict__ m) {
    __shared__ float wred[8];
    int n = blockIdx.x * blockDim.x + threadIdx.x;
    int b = n >> 12;
    int r = n & 4095;
    const float* p = z + ((size_t)b * C_DIM) * HW + r;
    float s = 0.0f, sa = 0.0f;
#pragma unroll 8
    for (int c = 0; c < C_DIM; c++) {
        float v = p[(size_t)c * HW];
        s = fmaf(v, v, s);
        sa += fabsf(v);
    }
    g_zz[n] = s;
    g_eps[n] = fmaf(2.5e-7f, sa, 1.5e-4f);   // validated fp16-probe bound
    g_amin[n] = 0xFFFFFFFFu;
    g_cnt[n] = 0u;
    if (n == 0) g_sumsq = 0.0f;

    float w = (m[n] == 0.0f) ? 1.0f : 0.0f;  // integer-valued: order-exact
#pragma unroll
    for (int o = 16; o; o >>= 1) w += __shfl_xor_sync(0xffffffffu, w, o);
    if ((threadIdx.x & 31) == 0) wred[threadIdx.x >> 5] = w;
    __syncthreads();
    if (threadIdx.x == 0) {
        float t = 0.0f;
#pragma unroll
        for (int i = 0; i < 8; i++) t += wred[i];
        g_wpart[blockIdx.x] = t;
    }
}

// ---------------- cb: ee[j] + fp16*2^13 conversion (one pass) ----------
__global__ void vq_cb_kernel(const float* __restrict__ cb) {
    int j    = (blockIdx.x * blockDim.x + threadIdx.x) >> 5;
    int lane = threadIdx.x & 31;
    const float4* p = (const float4*)(cb + (size_t)j * C_DIM);
    __half* hp = g_Bh + (size_t)j * C_DIM;
    float s = 0.0f;
#pragma unroll
    for (int i = 0; i < 4; i++) {
        float4 v = p[lane + 32 * i];
        s = fmaf(v.x, v.x, fmaf(v.y, v.y, fmaf(v.z, v.z, fmaf(v.w, v.w, s))));
        __half2* hq = (__half2*)(hp + (lane + 32 * i) * 4);
        hq[0] = __floats2half2_rn(v.x * 8192.0f, v.y * 8192.0f);
        hq[1] = __floats2half2_rn(v.z * 8192.0f, v.w * 8192.0f);
    }
#pragma unroll
    for (int o = 16; o; o >>= 1) s += __shfl_xor_sync(0xffffffffu, s, o);
    if (lane == 0) g_ee[j] = s;
}

// ---------------- z: NCHW -> [N,C] (fp32 zt + fp16 Ah) ----------------
__global__ void vq_zsplit_kernel(const float* __restrict__ z) {
    __shared__ float t[64][65];
    int bid = blockIdx.x;
    int hw0 = (bid & 63) * 64;
    int c0  = ((bid >> 6) & 7) * 64;
    int b   = bid >> 9;
    int tid = threadIdx.x;
    int q = tid >> 6;
    int l = tid & 63;
    const float* zp = z + ((size_t)b * C_DIM + c0) * HW + hw0;
#pragma unroll
    for (int s = 0; s < 16; s++) {
        int c = s * 4 + q;
        t[c][l] = zp[(size_t)c * HW + l];
    }
    __syncthreads();
    size_t rowbase = (size_t)b * HW + hw0;
#pragma unroll
    for (int s = 0; s < 16; s++) {
        int n = s * 4 + q;
        float a = t[l][n];
        size_t o = (rowbase + n) * C_DIM + c0 + l;
        g_zt[o] = a;
        g_Ah[o] = __float2half_rn(a);
    }
}

// ---------------- fp16 HMMA GEMM (KC=128) + tile-local candidate push ----
__global__ void __launch_bounds__(256, 1)
vq_mma_kernel() {
    extern __shared__ __align__(128) char sm[];
    const unsigned smb = (unsigned)__cvta_generic_to_shared(sm);

    const int tid  = threadIdx.x;
    const int lane = tid & 31;
    const int wid  = tid >> 5;
    const int wm   = wid >> 2;
    const int wn   = wid & 3;
    const int mblk = blockIdx.x >> 6;
    const int nblk = blockIdx.x & 63;

    const __half* Ahg = g_Ah + (size_t)(mblk * MT) * C_DIM;
    const __half* Bhg = g_Bh + (size_t)(nblk * NT) * C_DIM;

    const unsigned axor  = (unsigned)(lane & 7) << 4;
    const unsigned aoff  = (unsigned)(((lane & 7) + ((lane >> 3) & 1) * 8) * ROWB);
    const unsigned acolb = (unsigned)(((lane >> 4) & 1) * 16);
    const unsigned boff  = (unsigned)(((lane & 7) + ((lane >> 4) & 1) * 8) * ROWB);
    const unsigned bcolb = (unsigned)(((lane >> 3) & 1) * 16);

    float acc[4][4][4];
#pragma unroll
    for (int mt = 0; mt < 4; mt++)
#pragma unroll
        for (int nf = 0; nf < 4; nf++)
#pragma unroll
            for (int r = 0; r < 4; r++) acc[mt][nf][r] = 0.0f;

    // stage loader: 128 rows x 256B per tile; 16B chunk c of row swizzled by (row&7)
    auto load_stage = [&](int st, int k0) {
        const unsigned sb0 = smb + (unsigned)st * STAGE_BYTES;
#pragma unroll
        for (int i = 0; i < 8; i++) {
            int g = tid + 256 * i;
            int row = g >> 4;
            int c = g & 15;
            unsigned off = (unsigned)(row * ROWB) +
                           (((unsigned)(c * 16)) ^ ((unsigned)(row & 7) << 4));
            const size_t so = (size_t)row * C_DIM + k0 + c * 8;
            cpa16(sb0 + off, Ahg + so);
            cpa16(sb0 + TILE_BYTES + off, Bhg + so);
        }
        asm volatile("cp.async.commit_group;" ::: "memory");
    };

    load_stage(0, 0);
    load_stage(1, 1 * KC);

    for (int c = 0; c < NCHUNK; c++) {
        const int st = c % 3;
        if (c + 2 < NCHUNK) {
            load_stage((c + 2) % 3, (c + 2) * KC);
            asm volatile("cp.async.wait_group 2;" ::: "memory");
        } else if (c + 1 < NCHUNK) {
            asm volatile("cp.async.wait_group 1;" ::: "memory");
        } else {
            asm volatile("cp.async.wait_group 0;" ::: "memory");
        }
        __syncthreads();

        const unsigned sa = smb + (unsigned)st * STAGE_BYTES;
        const unsigned sb = sa + TILE_BYTES;
#pragma unroll
        for (int ks = 0; ks < 8; ks++) {       // 8 x k16 = KC 128
            unsigned af[4][4];
#pragma unroll
            for (int mt = 0; mt < 4; mt++) {
                unsigned addr = sa + (unsigned)((wm * 64 + mt * 16) * ROWB) + aoff
                                + (((unsigned)(ks * 32) + acolb) ^ axor);
                ldsm4(af[mt][0], af[mt][1], af[mt][2], af[mt][3], addr);
            }
            unsigned bf[4][2];
#pragma unroll
            for (int g2 = 0; g2 < 2; g2++) {
                unsigned addr = sb + (unsigned)((wn * 32 + g2 * 16) * ROWB) + boff
                                + (((unsigned)(ks * 32) + bcolb) ^ axor);
                ldsm4(bf[g2 * 2][0], bf[g2 * 2][1],
                      bf[g2 * 2 + 1][0], bf[g2 * 2 + 1][1], addr);
            }
#pragma unroll
            for (int mt = 0; mt < 4; mt++)
#pragma unroll
                for (int nf = 0; nf < 4; nf++)
                    MMA_F16(acc[mt][nf], af[mt], bf[nf]);
        }
        __syncthreads();
    }

    // ---- epilogue pass 1: s = ee - acc/4096 in place + per-row mins ----
    float* sRedF = (float*)sm;
    float* sThr  = (float*)(sm + 2048);

#pragma unroll
    for (int mt = 0; mt < 4; mt++) {
        float mn[2] = { __int_as_float(0x7f800000), __int_as_float(0x7f800000) };
#pragma unroll
        for (int nf = 0; nf < 4; nf++) {
#pragma unroll
            for (int r = 0; r < 4; r++) {
                const int n = nblk * NT + wn * 32 + nf * 8 + (lane & 3) * 2 + (r & 1);
                float s = fmaf(-INV4096, acc[mt][nf][r], __ldg(&g_ee[n]));
                acc[mt][nf][r] = s;
                mn[r >> 1] = fminf(mn[r >> 1], s);
            }
        }
#pragma unroll
        for (int rh = 0; rh < 2; rh++) {
            float v = mn[rh];
#pragma unroll
            for (int o = 1; o <= 2; o <<= 1)
                v = fminf(v, __shfl_xor_sync(0xffffffffu, v, o));
            if ((lane & 3) == 0)
                sRedF[wn * 128 + wm * 64 + mt * 16 + (lane >> 2) + rh * 8] = v;
        }
    }
    __syncthreads();
    if (tid < 128) {
        float mn = sRedF[tid];
#pragma unroll
        for (int w = 1; w < 4; w++) mn = fminf(mn, sRedF[w * 128 + tid]);
        const int rowg = mblk * MT + tid;
        atomicMin(&g_amin[rowg], msk(mn));
        sThr[tid] = mn + 2.0f * g_eps[rowg];
    }
    __syncthreads();

    // ---- epilogue pass 2: push from regs ----
#pragma unroll
    for (int mt = 0; mt < 4; mt++) {
#pragma unroll
        for (int rh = 0; rh < 2; rh++) {
            const int mloc = wm * 64 + mt * 16 + (lane >> 2) + rh * 8;
            const float thr = sThr[mloc];
            const int rowg = mblk * MT + mloc;
#pragma unroll
            for (int nf = 0; nf < 4; nf++) {
#pragma unroll
                for (int q = 0; q < 2; q++) {
                    float s = acc[mt][nf][rh * 2 + q];
                    if (s <= thr) {
                        const int n = nblk * NT + wn * 32 + nf * 8 + (lane & 3) * 2 + q;
                        unsigned idx = atomicAdd(&g_cnt[rowg], 1u);
                        if (idx < CAP)
                            g_cand[(size_t)rowg * CAP + idx] =
                                ((unsigned long long)msk(s) << 32) | (unsigned)n;
                    }
                }
            }
        }
    }
}

// ---------------- resolve + output + idx (fused) ----------------
__global__ void __launch_bounds__(256)
vq_resolve_kernel(const float* __restrict__ cb, const float* __restrict__ m,
                  float* __restrict__ out) {
    const int row  = blockIdx.x * 8 + (threadIdx.x >> 5);
    const int lane = threadIdx.x & 31;

    const unsigned rawcnt = g_cnt[row];
    const bool ovf = rawcnt > CAP;
    const int cnt = ovf ? CAP : (int)rawcnt;
    const float aminv = msk_inv(g_amin[row]);
    const unsigned thr = msk(aminv + 2.0f * g_eps[row]);

    float zreg[16];
    {
        const float4* zp = (const float4*)(g_zt + (size_t)row * C_DIM + lane * 16);
#pragma unroll
        for (int q = 0; q < 4; q++) {
            float4 v = zp[q];
            zreg[q * 4 + 0] = v.x; zreg[q * 4 + 1] = v.y;
            zreg[q * 4 + 2] = v.z; zreg[q * 4 + 3] = v.w;
        }
    }
    const float zz = g_zz[row];
    unsigned long long best = ~0ull;

    auto exact_eval = [&](int j) {
        const float4* cp = (const float4*)(cb + (size_t)j * C_DIM + lane * 16);
        float d = 0.0f;
#pragma unroll
        for (int q = 0; q < 4; q++) {
            float4 cv = __ldg(cp + q);
            d = fmaf(zreg[q * 4 + 0], cv.x, d);
            d = fmaf(zreg[q * 4 + 1], cv.y, d);
            d = fmaf(zreg[q * 4 + 2], cv.z, d);
            d = fmaf(zreg[q * 4 + 3], cv.w, d);
        }
#pragma unroll
        for (int o = 16; o; o >>= 1) d += __shfl_xor_sync(0xffffffffu, d, o);
        float ve = __fsub_rn(__fadd_rn(zz, __ldg(&g_ee[j])), 2.0f * d);
        unsigned long long pv =
            ((unsigned long long)__float_as_uint(ve) << 32) | (unsigned)j;
        if (pv < best) best = pv;
    };

    if (!ovf) {
        const unsigned long long* cl = g_cand + (size_t)row * CAP;
        for (int i = 0; i < cnt; i++) {
            unsigned long long e = cl[i];
            if ((unsigned)(e >> 32) <= thr)
                exact_eval((int)(e & 0xffffffffu));
        }
    } else {
        for (int j = 0; j < NE; j++) exact_eval(j);
    }

    const int j = (int)(best & 0xffffffffu);
    const float4* cq = (const float4*)(cb + (size_t)j * C_DIM + lane * 16);
    float4* op = (float4*)(out + (size_t)row * C_DIM + lane * 16);
    float ssq = 0.0f;
#pragma unroll
    for (int q = 0; q < 4; q++) {
        float4 cv = __ldg(cq + q);
        float4 o;
        float t;
        t = cv.x - zreg[q * 4 + 0]; ssq = fmaf(t, t, ssq); o.x = zreg[q * 4 + 0] + t;
        t = cv.y - zreg[q * 4 + 1]; ssq = fmaf(t, t, ssq); o.y = zreg[q * 4 + 1] + t;
        t = cv.z - zreg[q * 4 + 2]; ssq = fmaf(t, t, ssq); o.z = zreg[q * 4 + 2] + t;
        t = cv.w - zreg[q * 4 + 3]; ssq = fmaf(t, t, ssq); o.w = zreg[q * 4 + 3] + t;
        op[q] = o;
    }
#pragma unroll
    for (int o = 16; o; o >>= 1) ssq += __shfl_xor_sync(0xffffffffu, ssq, o);
    if (lane == 0) {
        if (m[row] == 0.0f) atomicAdd(&g_sumsq, ssq);
        out[(size_t)N_ROWS * C_DIM + 1 + row] = (float)j;
    }
}

// ---------------- scalar loss (deterministic wpart sum) --------------
__global__ void vq_finalize_kernel(float* __restrict__ out) {
    int lane = threadIdx.x & 31;
    float w = 0.0f;
#pragma unroll
    for (int i = 0; i < 4; i++) w += g_wpart[lane + 32 * i];
#pragma unroll
    for (int o = 16; o; o >>= 1) w += __shfl_xor_sync(0xffffffffu, w, o);
    if (lane == 0)
        out[(size_t)N_ROWS * C_DIM] = (1.0f + BETA_F) * g_sumsq / (w * (float)C_DIM);
}

// ---------------- launch ----------------
extern "C" void kernel_launch(void* const* d_in, const int* in_sizes, int n_in,
                              void* d_out, int out_size) {
    (void)in_sizes; (void)n_in; (void)out_size;
    const float* z  = (const float*)d_in[0];
    const float* m  = (const float*)d_in[1];
    const float* cb = (const float*)d_in[2];
    float* out = (float*)d_out;

    cudaFuncSetAttribute(vq_mma_kernel,
                         cudaFuncAttributeMaxDynamicSharedMemorySize, SMEM_TOTAL);

    vq_prep_kernel<<<N_ROWS / 256, 256>>>(z, m);
    vq_cb_kernel<<<NE * 32 / 256, 256>>>(cb);
    vq_zsplit_kernel<<<4096, 256>>>(z);
    vq_mma_kernel<<<MBLK * NBLK, 256, SMEM_TOTAL>>>();
    vq_resolve_kernel<<<N_ROWS / 8, 256>>>(cb, m, out);
    vq_finalize_kernel<<<1, 32>>>(out);
}

// round 15
// speedup vs baseline: 1.8159x; 1.8159x over previous
#include <cuda_runtime.h>
#include <cuda_fp16.h>

#define N_ROWS 32768
#define C_DIM  512
#define NE     8192
#define HW     4096
#define BETA_F 0.25f

// GEMM tiling: CTA 128x128 (512 threads), warp 32x32, KC=64
#define MT 128
#define NT 128
#define KC 64
#define NCHUNK (C_DIM / KC)     // 8
#define NBLK   (NE / NT)        // 64
#define MBLK   (N_ROWS / MT)    // 256

#define STAGE_BYTES 32768u
#define TILE_BYTES  16384u
#define SMEM_TOTAL  98304       // 3 stages

#define CAP 512
#define INV4096 2.44140625e-4f  // 2^-12, exact

// ---------------- device scratch ----------------
__device__ float g_zz[N_ROWS];
__device__ float g_eps[N_ROWS];
__device__ float g_ee[NE];
__device__ unsigned g_amin[N_ROWS];
__device__ unsigned g_cnt[N_ROWS];
__device__ unsigned long long g_cand[(size_t)N_ROWS * CAP];
__device__ float g_wpart[N_ROWS / 256];
__device__ float g_sumsq;
__device__ __half g_Ah[(size_t)N_ROWS * C_DIM];
__device__ __half g_Bh[(size_t)NE * C_DIM];          // codebook * 2^13
__device__ float g_zt[(size_t)N_ROWS * C_DIM];

// ---------------- helpers ----------------
__device__ __forceinline__ void cpa16(unsigned dst, const void* src) {
    asm volatile("cp.async.cg.shared.global [%0], [%1], 16;" :: "r"(dst), "l"(src));
}
__device__ __forceinline__ void ldsm4(unsigned &r0, unsigned &r1, unsigned &r2,
                                      unsigned &r3, unsigned addr) {
    asm volatile("ldmatrix.sync.aligned.m8n8.x4.shared.b16 {%0,%1,%2,%3},[%4];"
                 : "=r"(r0), "=r"(r1), "=r"(r2), "=r"(r3) : "r"(addr));
}
#define MMA_F16(d, a, b) \
    asm volatile("mma.sync.aligned.m16n8k16.row.col.f32.f16.f16.f32 " \
        "{%0,%1,%2,%3},{%4,%5,%6,%7},{%8,%9},{%0,%1,%2,%3};" \
        : "+f"((d)[0]), "+f"((d)[1]), "+f"((d)[2]), "+f"((d)[3]) \
        : "r"((a)[0]), "r"((a)[1]), "r"((a)[2]), "r"((a)[3]), \
          "r"((b)[0]), "r"((b)[1]))

__device__ __forceinline__ unsigned msk(float s) {
    unsigned b = __float_as_uint(s);
    return b ^ ((b & 0x80000000u) ? 0xFFFFFFFFu : 0x80000000u);
}
__device__ __forceinline__ float msk_inv(unsigned v) {
    return (v & 0x80000000u) ? __uint_as_float(v ^ 0x80000000u)
                             : __uint_as_float(~v);
}

// ---------------- prep: zz, eps, init, mask partials ----------------
__global__ void vq_prep_kernel(const float* __restrict__ z,
                               const float* __restrict__ m) {
    __shared__ float wred[8];
    int n = blockIdx.x * blockDim.x + threadIdx.x;
    int b = n >> 12;
    int r = n & 4095;
    const float* p = z + ((size_t)b * C_DIM) * HW + r;
    float s = 0.0f, sa = 0.0f;
#pragma unroll 8
    for (int c = 0; c < C_DIM; c++) {
        float v = p[(size_t)c * HW];
        s = fmaf(v, v, s);
        sa += fabsf(v);
    }
    g_zz[n] = s;
    g_eps[n] = fmaf(2.5e-7f, sa, 1.5e-4f);   // validated fp16-probe bound
    g_amin[n] = 0xFFFFFFFFu;
    g_cnt[n] = 0u;
    if (n == 0) g_sumsq = 0.0f;

    float w = (m[n] == 0.0f) ? 1.0f : 0.0f;  // integer-valued: order-exact
#pragma unroll
    for (int o = 16; o; o >>= 1) w += __shfl_xor_sync(0xffffffffu, w, o);
    if ((threadIdx.x & 31) == 0) wred[threadIdx.x >> 5] = w;
    __syncthreads();
    if (threadIdx.x == 0) {
        float t = 0.0f;
#pragma unroll
        for (int i = 0; i < 8; i++) t += wred[i];
        g_wpart[blockIdx.x] = t;
    }
}

// ---------------- cb: ee[j] + fp16*2^13 conversion (one pass) ----------
__global__ void vq_cb_kernel(const float* __restrict__ cb) {
    int j    = (blockIdx.x * blockDim.x + threadIdx.x) >> 5;
    int lane = threadIdx.x & 31;
    const float4* p = (const float4*)(cb + (size_t)j * C_DIM);
    __half* hp = g_Bh + (size_t)j * C_DIM;
    float s = 0.0f;
#pragma unroll
    for (int i = 0; i < 4; i++) {
        float4 v = p[lane + 32 * i];
        s = fmaf(v.x, v.x, fmaf(v.y, v.y, fmaf(v.z, v.z, fmaf(v.w, v.w, s))));
        __half2* hq = (__half2*)(hp + (lane + 32 * i) * 4);
        hq[0] = __floats2half2_rn(v.x * 8192.0f, v.y * 8192.0f);
        hq[1] = __floats2half2_rn(v.z * 8192.0f, v.w * 8192.0f);
    }
#pragma unroll
    for (int o = 16; o; o >>= 1) s += __shfl_xor_sync(0xffffffffu, s, o);
    if (lane == 0) g_ee[j] = s;
}

// ---------------- z: NCHW -> [N,C] (fp32 zt + fp16 Ah) ----------------
__global__ void vq_zsplit_kernel(const float* __restrict__ z) {
    __shared__ float t[64][65];
    int bid = blockIdx.x;
    int hw0 = (bid & 63) * 64;
    int c0  = ((bid >> 6) & 7) * 64;
    int b   = bid >> 9;
    int tid = threadIdx.x;
    int q = tid >> 6;
    int l = tid & 63;
    const float* zp = z + ((size_t)b * C_DIM + c0) * HW + hw0;
#pragma unroll
    for (int s = 0; s < 16; s++) {
        int c = s * 4 + q;
        t[c][l] = zp[(size_t)c * HW + l];
    }
    __syncthreads();
    size_t rowbase = (size_t)b * HW + hw0;
#pragma unroll
    for (int s = 0; s < 16; s++) {
        int n = s * 4 + q;
        float a = t[l][n];
        size_t o = (rowbase + n) * C_DIM + c0 + l;
        g_zt[o] = a;
        g_Ah[o] = __float2half_rn(a);
    }
}

// ---------------- fp16 HMMA GEMM (512thr, warp 32x32) + candidate push ---
__global__ void __launch_bounds__(512, 2)
vq_mma_kernel() {
    extern __shared__ __align__(128) char sm[];
    const unsigned smb = (unsigned)__cvta_generic_to_shared(sm);

    const int tid  = threadIdx.x;
    const int lane = tid & 31;
    const int wid  = tid >> 5;        // 0..15
    const int wm   = wid >> 2;        // 0..3 (32 rows each)
    const int wn   = wid & 3;         // 0..3 (32 cols each)
    const int mblk = blockIdx.x >> 6;
    const int nblk = blockIdx.x & 63;

    const __half* Ahg = g_Ah + (size_t)(mblk * MT) * C_DIM;
    const __half* Bhg = g_Bh + (size_t)(nblk * NT) * C_DIM;

    const unsigned axor  = (unsigned)(lane & 7) << 4;
    const unsigned aoff  = (unsigned)(((lane & 7) + ((lane >> 3) & 1) * 8) * 128);
    const unsigned acolb = (unsigned)(((lane >> 4) & 1) * 16);
    const unsigned boff  = (unsigned)(((lane & 7) + ((lane >> 4) & 1) * 8) * 128);
    const unsigned bcolb = (unsigned)(((lane >> 3) & 1) * 16);

    float acc[2][4][4];
#pragma unroll
    for (int mt = 0; mt < 2; mt++)
#pragma unroll
        for (int nf = 0; nf < 4; nf++)
#pragma unroll
            for (int r = 0; r < 4; r++) acc[mt][nf][r] = 0.0f;

    // stage loader: 512 threads, 2 iterations cover 128 rows x 8 chunks
    auto load_stage = [&](int st, int k0) {
        const unsigned sb0 = smb + (unsigned)st * STAGE_BYTES;
#pragma unroll
        for (int i = 0; i < 2; i++) {
            int g = tid + 512 * i;
            int row = g >> 3;
            int c = g & 7;
            unsigned off = (unsigned)(row * 128) +
                           (((unsigned)(c * 16)) ^ ((unsigned)(row & 7) << 4));
            const size_t so = (size_t)row * C_DIM + k0 + c * 8;
            cpa16(sb0 + off, Ahg + so);
            cpa16(sb0 + TILE_BYTES + off, Bhg + so);
        }
        asm volatile("cp.async.commit_group;" ::: "memory");
    };

    load_stage(0, 0);
    load_stage(1, 1 * KC);

    for (int c = 0; c < NCHUNK; c++) {
        const int st = c % 3;
        if (c + 2 < NCHUNK) {
            load_stage((c + 2) % 3, (c + 2) * KC);
            asm volatile("cp.async.wait_group 2;" ::: "memory");
        } else if (c + 1 < NCHUNK) {
            asm volatile("cp.async.wait_group 1;" ::: "memory");
        } else {
            asm volatile("cp.async.wait_group 0;" ::: "memory");
        }
        __syncthreads();

        const unsigned sa = smb + (unsigned)st * STAGE_BYTES;
        const unsigned sb = sa + TILE_BYTES;
#pragma unroll
        for (int ks = 0; ks < 4; ks++) {
            unsigned bf[4][2];
#pragma unroll
            for (int g2 = 0; g2 < 2; g2++) {
                unsigned addr = sb + (unsigned)((wn * 32 + g2 * 16) * 128) + boff
                                + (((unsigned)(ks * 32) + bcolb) ^ axor);
                ldsm4(bf[g2 * 2][0], bf[g2 * 2][1],
                      bf[g2 * 2 + 1][0], bf[g2 * 2 + 1][1], addr);
            }
            unsigned af[2][4];
#pragma unroll
            for (int mt = 0; mt < 2; mt++) {
                unsigned addr = sa + (unsigned)((wm * 32 + mt * 16) * 128) + aoff
                                + (((unsigned)(ks * 32) + acolb) ^ axor);
                ldsm4(af[mt][0], af[mt][1], af[mt][2], af[mt][3], addr);
            }
#pragma unroll
            for (int mt = 0; mt < 2; mt++)
#pragma unroll
                for (int nf = 0; nf < 4; nf++)
                    MMA_F16(acc[mt][nf], af[mt], bf[nf]);
        }
        __syncthreads();
    }

    // ---- epilogue pass 1: s = ee - acc/4096 in place + per-row mins ----
    float* sRedF = (float*)sm;                    // [4][128]
    float* sThr  = (float*)(sm + 2048);           // [128]

#pragma unroll
    for (int mt = 0; mt < 2; mt++) {
        float mn[2] = { __int_as_float(0x7f800000), __int_as_float(0x7f800000) };
#pragma unroll
        for (int nf = 0; nf < 4; nf++) {
#pragma unroll
            for (int r = 0; r < 4; r++) {
                const int n = nblk * NT + wn * 32 + nf * 8 + (lane & 3) * 2 + (r & 1);
                float s = fmaf(-INV4096, acc[mt][nf][r], __ldg(&g_ee[n]));
                acc[mt][nf][r] = s;
                mn[r >> 1] = fminf(mn[r >> 1], s);
            }
        }
#pragma unroll
        for (int rh = 0; rh < 2; rh++) {
            float v = mn[rh];
#pragma unroll
            for (int o = 1; o <= 2; o <<= 1)
                v = fminf(v, __shfl_xor_sync(0xffffffffu, v, o));
            if ((lane & 3) == 0)
                sRedF[wn * 128 + wm * 32 + mt * 16 + (lane >> 2) + rh * 8] = v;
        }
    }
    __syncthreads();
    if (tid < 128) {
        float mn = sRedF[tid];
#pragma unroll
        for (int w = 1; w < 4; w++) mn = fminf(mn, sRedF[w * 128 + tid]);
        const int rowg = mblk * MT + tid;
        atomicMin(&g_amin[rowg], msk(mn));
        sThr[tid] = mn + 2.0f * g_eps[rowg];
    }
    __syncthreads();

    // ---- epilogue pass 2: push from regs ----
#pragma unroll
    for (int mt = 0; mt < 2; mt++) {
#pragma unroll
        for (int rh = 0; rh < 2; rh++) {
            const int mloc = wm * 32 + mt * 16 + (lane >> 2) + rh * 8;
            const float thr = sThr[mloc];
            const int rowg = mblk * MT + mloc;
#pragma unroll
            for (int nf = 0; nf < 4; nf++) {
#pragma unroll
                for (int q = 0; q < 2; q++) {
                    float s = acc[mt][nf][rh * 2 + q];
                    if (s <= thr) {
                        const int n = nblk * NT + wn * 32 + nf * 8 + (lane & 3) * 2 + q;
                        unsigned idx = atomicAdd(&g_cnt[rowg], 1u);
                        if (idx < CAP)
                            g_cand[(size_t)rowg * CAP + idx] =
                                ((unsigned long long)msk(s) << 32) | (unsigned)n;
                    }
                }
            }
        }
    }
}

// ---------------- resolve + output + idx (fused) ----------------
__global__ void __launch_bounds__(256)
vq_resolve_kernel(const float* __restrict__ cb, const float* __restrict__ m,
                  float* __restrict__ out) {
    const int row  = blockIdx.x * 8 + (threadIdx.x >> 5);
    const int lane = threadIdx.x & 31;

    const unsigned rawcnt = g_cnt[row];
    const bool ovf = rawcnt > CAP;
    const int cnt = ovf ? CAP : (int)rawcnt;
    const float aminv = msk_inv(g_amin[row]);
    const unsigned thr = msk(aminv + 2.0f * g_eps[row]);

    float zreg[16];
    {
        const float4* zp = (const float4*)(g_zt + (size_t)row * C_DIM + lane * 16);
#pragma unroll
        for (int q = 0; q < 4; q++) {
            float4 v = zp[q];
            zreg[q * 4 + 0] = v.x; zreg[q * 4 + 1] = v.y;
            zreg[q * 4 + 2] = v.z; zreg[q * 4 + 3] = v.w;
        }
    }
    const float zz = g_zz[row];
    unsigned long long best = ~0ull;

    auto exact_eval = [&](int j) {
        const float4* cp = (const float4*)(cb + (size_t)j * C_DIM + lane * 16);
        float d = 0.0f;
#pragma unroll
        for (int q = 0; q < 4; q++) {
            float4 cv = __ldg(cp + q);
            d = fmaf(zreg[q * 4 + 0], cv.x, d);
            d = fmaf(zreg[q * 4 + 1], cv.y, d);
            d = fmaf(zreg[q * 4 + 2], cv.z, d);
            d = fmaf(zreg[q * 4 + 3], cv.w, d);
        }
#pragma unroll
        for (int o = 16; o; o >>= 1) d += __shfl_xor_sync(0xffffffffu, d, o);
        float ve = __fsub_rn(__fadd_rn(zz, __ldg(&g_ee[j])), 2.0f * d);
        unsigned long long pv =
            ((unsigned long long)__float_as_uint(ve) << 32) | (unsigned)j;
        if (pv < best) best = pv;
    };

    if (!ovf) {
        const unsigned long long* cl = g_cand + (size_t)row * CAP;
        for (int i = 0; i < cnt; i++) {
            unsigned long long e = cl[i];
            if ((unsigned)(e >> 32) <= thr)
                exact_eval((int)(e & 0xffffffffu));
        }
    } else {
        for (int j = 0; j < NE; j++) exact_eval(j);
    }

    const int j = (int)(best & 0xffffffffu);
    const float4* cq = (const float4*)(cb + (size_t)j * C_DIM + lane * 16);
    float4* op = (float4*)(out + (size_t)row * C_DIM + lane * 16);
    float ssq = 0.0f;
#pragma unroll
    for (int q = 0; q < 4; q++) {
        float4 cv = __ldg(cq + q);
        float4 o;
        float t;
        t = cv.x - zreg[q * 4 + 0]; ssq = fmaf(t, t, ssq); o.x = zreg[q * 4 + 0] + t;
        t = cv.y - zreg[q * 4 + 1]; ssq = fmaf(t, t, ssq); o.y = zreg[q * 4 + 1] + t;
        t = cv.z - zreg[q * 4 + 2]; ssq = fmaf(t, t, ssq); o.z = zreg[q * 4 + 2] + t;
        t = cv.w - zreg[q * 4 + 3]; ssq = fmaf(t, t, ssq); o.w = zreg[q * 4 + 3] + t;
        op[q] = o;
    }
#pragma unroll
    for (int o = 16; o; o >>= 1) ssq += __shfl_xor_sync(0xffffffffu, ssq, o);
    if (lane == 0) {
        if (m[row] == 0.0f) atomicAdd(&g_sumsq, ssq);
        out[(size_t)N_ROWS * C_DIM + 1 + row] = (float)j;
    }
}

// ---------------- scalar loss (deterministic wpart sum) --------------
__global__ void vq_finalize_kernel(float* __restrict__ out) {
    int lane = threadIdx.x & 31;
    float w = 0.0f;
#pragma unroll
    for (int i = 0; i < 4; i++) w += g_wpart[lane + 32 * i];
#pragma unroll
    for (int o = 16; o; o >>= 1) w += __shfl_xor_sync(0xffffffffu, w, o);
    if (lane == 0)
        out[(size_t)N_ROWS * C_DIM] = (1.0f + BETA_F) * g_sumsq / (w * (float)C_DIM);
}

// ---------------- launch ----------------
extern "C" void kernel_launch(void* const* d_in, const int* in_sizes, int n_in,
                              void* d_out, int out_size) {
    (void)in_sizes; (void)n_in; (void)out_size;
    const float* z  = (const float*)d_in[0];
    const float* m  = (const float*)d_in[1];
    const float* cb = (const float*)d_in[2];
    float* out = (float*)d_out;

    cudaFuncSetAttribute(vq_mma_kernel,
                         cudaFuncAttributeMaxDynamicSharedMemorySize, SMEM_TOTAL);

    vq_prep_kernel<<<N_ROWS / 256, 256>>>(z, m);
    vq_cb_kernel<<<NE * 32 / 256, 256>>>(cb);
    vq_zsplit_kernel<<<4096, 256>>>(z);
    vq_mma_kernel<<<MBLK * NBLK, 512, SMEM_TOTAL>>>();
    vq_resolve_kernel<<<N_ROWS / 8, 256>>>(cb, m, out);
    vq_finalize_kernel<<<1, 32>>>(out);
}

// round 16
// speedup vs baseline: 1.8497x; 1.0186x over previous
#include <cuda_runtime.h>
#include <cuda_fp16.h>

#define N_ROWS 32768
#define C_DIM  512
#define NE     8192
#define HW     4096
#define BETA_F 0.25f

// GEMM tiling: CTA 128x128 (512 threads), warp 32x32, KC=64
#define MT 128
#define NT 128
#define KC 64
#define NCHUNK (C_DIM / KC)     // 8
#define NBLK   (NE / NT)        // 64
#define MBLK   (N_ROWS / MT)    // 256

#define STAGE_BYTES 32768u
#define TILE_BYTES  16384u
#define SMEM_TOTAL  98304       // 3 stages

#define CAP 512
#define INV4096 2.44140625e-4f  // 2^-12, exact

// ---------------- device scratch ----------------
__device__ float g_zz[N_ROWS];
__device__ float g_eps[N_ROWS];
__device__ float g_ee[NE];
__device__ unsigned g_amin[N_ROWS];
__device__ unsigned g_cnt[N_ROWS];
__device__ unsigned long long g_cand[(size_t)N_ROWS * CAP];
__device__ float g_wpart[N_ROWS / 256];
__device__ float g_sumsq;
__device__ __half g_Ah[(size_t)N_ROWS * C_DIM];
__device__ __half g_Bh[(size_t)NE * C_DIM];          // codebook * 2^13
__device__ float g_zt[(size_t)N_ROWS * C_DIM];

// ---------------- helpers ----------------
__device__ __forceinline__ void cpa16(unsigned dst, const void* src) {
    asm volatile("cp.async.cg.shared.global [%0], [%1], 16;" :: "r"(dst), "l"(src));
}
__device__ __forceinline__ void ldsm4(unsigned &r0, unsigned &r1, unsigned &r2,
                                      unsigned &r3, unsigned addr) {
    asm volatile("ldmatrix.sync.aligned.m8n8.x4.shared.b16 {%0,%1,%2,%3},[%4];"
                 : "=r"(r0), "=r"(r1), "=r"(r2), "=r"(r3) : "r"(addr));
}
#define MMA_F16(d, a, b) \
    asm volatile("mma.sync.aligned.m16n8k16.row.col.f32.f16.f16.f32 " \
        "{%0,%1,%2,%3},{%4,%5,%6,%7},{%8,%9},{%0,%1,%2,%3};" \
        : "+f"((d)[0]), "+f"((d)[1]), "+f"((d)[2]), "+f"((d)[3]) \
        : "r"((a)[0]), "r"((a)[1]), "r"((a)[2]), "r"((a)[3]), \
          "r"((b)[0]), "r"((b)[1]))

__device__ __forceinline__ unsigned msk(float s) {
    unsigned b = __float_as_uint(s);
    return b ^ ((b & 0x80000000u) ? 0xFFFFFFFFu : 0x80000000u);
}
__device__ __forceinline__ float msk_inv(unsigned v) {
    return (v & 0x80000000u) ? __uint_as_float(v ^ 0x80000000u)
                             : __uint_as_float(~v);
}

// ---------------- prep: zz, eps, init, mask partials ----------------
__global__ void vq_prep_kernel(const float* __restrict__ z,
                               const float* __restrict__ m) {
    __shared__ float wred[8];
    int n = blockIdx.x * blockDim.x + threadIdx.x;
    int b = n >> 12;
    int r = n & 4095;
    const float* p = z + ((size_t)b * C_DIM) * HW + r;
    float s = 0.0f, sa = 0.0f;
#pragma unroll 8
    for (int c = 0; c < C_DIM; c++) {
        float v = p[(size_t)c * HW];
        s = fmaf(v, v, s);
        sa += fabsf(v);
    }
    g_zz[n] = s;
    g_eps[n] = fmaf(2.5e-7f, sa, 1.5e-4f);   // validated fp16-probe bound
    g_amin[n] = 0xFFFFFFFFu;
    g_cnt[n] = 0u;
    if (n == 0) g_sumsq = 0.0f;

    float w = (m[n] == 0.0f) ? 1.0f : 0.0f;  // integer-valued: order-exact
#pragma unroll
    for (int o = 16; o; o >>= 1) w += __shfl_xor_sync(0xffffffffu, w, o);
    if ((threadIdx.x & 31) == 0) wred[threadIdx.x >> 5] = w;
    __syncthreads();
    if (threadIdx.x == 0) {
        float t = 0.0f;
#pragma unroll
        for (int i = 0; i < 8; i++) t += wred[i];
        g_wpart[blockIdx.x] = t;
    }
}

// ---------------- cb: ee[j] + fp16*2^13 conversion (one pass) ----------
__global__ void vq_cb_kernel(const float* __restrict__ cb) {
    int j    = (blockIdx.x * blockDim.x + threadIdx.x) >> 5;
    int lane = threadIdx.x & 31;
    const float4* p = (const float4*)(cb + (size_t)j * C_DIM);
    __half* hp = g_Bh + (size_t)j * C_DIM;
    float s = 0.0f;
#pragma unroll
    for (int i = 0; i < 4; i++) {
        float4 v = p[lane + 32 * i];
        s = fmaf(v.x, v.x, fmaf(v.y, v.y, fmaf(v.z, v.z, fmaf(v.w, v.w, s))));
        __half2* hq = (__half2*)(hp + (lane + 32 * i) * 4);
        hq[0] = __floats2half2_rn(v.x * 8192.0f, v.y * 8192.0f);
        hq[1] = __floats2half2_rn(v.z * 8192.0f, v.w * 8192.0f);
    }
#pragma unroll
    for (int o = 16; o; o >>= 1) s += __shfl_xor_sync(0xffffffffu, s, o);
    if (lane == 0) g_ee[j] = s;
}

// ---------------- z: NCHW -> [N,C] (fp32 zt + fp16 Ah) ----------------
__global__ void vq_zsplit_kernel(const float* __restrict__ z) {
    __shared__ float t[64][65];
    int bid = blockIdx.x;
    int hw0 = (bid & 63) * 64;
    int c0  = ((bid >> 6) & 7) * 64;
    int b   = bid >> 9;
    int tid = threadIdx.x;
    int q = tid >> 6;
    int l = tid & 63;
    const float* zp = z + ((size_t)b * C_DIM + c0) * HW + hw0;
#pragma unroll
    for (int s = 0; s < 16; s++) {
        int c = s * 4 + q;
        t[c][l] = zp[(size_t)c * HW + l];
    }
    __syncthreads();
    size_t rowbase = (size_t)b * HW + hw0;
#pragma unroll
    for (int s = 0; s < 16; s++) {
        int n = s * 4 + q;
        float a = t[l][n];
        size_t o = (rowbase + n) * C_DIM + c0 + l;
        g_zt[o] = a;
        g_Ah[o] = __float2half_rn(a);
    }
}

// ---------------- fp16 HMMA GEMM (512thr, single-sync loop) --------------
__global__ void __launch_bounds__(512, 2)
vq_mma_kernel() {
    extern __shared__ __align__(128) char sm[];
    const unsigned smb = (unsigned)__cvta_generic_to_shared(sm);

    const int tid  = threadIdx.x;
    const int lane = tid & 31;
    const int wid  = tid >> 5;        // 0..15
    const int wm   = wid >> 2;        // 0..3 (32 rows each)
    const int wn   = wid & 3;         // 0..3 (32 cols each)
    const int mblk = blockIdx.x >> 6;
    const int nblk = blockIdx.x & 63;

    const __half* Ahg = g_Ah + (size_t)(mblk * MT) * C_DIM;
    const __half* Bhg = g_Bh + (size_t)(nblk * NT) * C_DIM;

    const unsigned axor  = (unsigned)(lane & 7) << 4;
    const unsigned aoff  = (unsigned)(((lane & 7) + ((lane >> 3) & 1) * 8) * 128);
    const unsigned acolb = (unsigned)(((lane >> 4) & 1) * 16);
    const unsigned boff  = (unsigned)(((lane & 7) + ((lane >> 4) & 1) * 8) * 128);
    const unsigned bcolb = (unsigned)(((lane >> 3) & 1) * 16);

    float acc[2][4][4];
#pragma unroll
    for (int mt = 0; mt < 2; mt++)
#pragma unroll
        for (int nf = 0; nf < 4; nf++)
#pragma unroll
            for (int r = 0; r < 4; r++) acc[mt][nf][r] = 0.0f;

    auto load_stage = [&](int st, int k0) {
        const unsigned sb0 = smb + (unsigned)st * STAGE_BYTES;
#pragma unroll
        for (int i = 0; i < 2; i++) {
            int g = tid + 512 * i;
            int row = g >> 3;
            int c = g & 7;
            unsigned off = (unsigned)(row * 128) +
                           (((unsigned)(c * 16)) ^ ((unsigned)(row & 7) << 4));
            const size_t so = (size_t)row * C_DIM + k0 + c * 8;
            cpa16(sb0 + off, Ahg + so);
            cpa16(sb0 + TILE_BYTES + off, Bhg + so);
        }
        asm volatile("cp.async.commit_group;" ::: "memory");
    };

    load_stage(0, 0);
    load_stage(1, 1 * KC);

    // single-sync multistage: wait(c ready) -> sync (all done reading the
    // buffer about to be overwritten) -> issue load(c+2) -> mma(c)
    for (int c = 0; c < NCHUNK; c++) {
        const int st = c % 3;
        if (c + 1 < NCHUNK) {
            asm volatile("cp.async.wait_group 1;" ::: "memory");
        } else {
            asm volatile("cp.async.wait_group 0;" ::: "memory");
        }
        __syncthreads();
        if (c + 2 < NCHUNK)
            load_stage((c + 2) % 3, (c + 2) * KC);

        const unsigned sa = smb + (unsigned)st * STAGE_BYTES;
        const unsigned sb = sa + TILE_BYTES;
#pragma unroll
        for (int ks = 0; ks < 4; ks++) {
            unsigned bf[4][2];
#pragma unroll
            for (int g2 = 0; g2 < 2; g2++) {
                unsigned addr = sb + (unsigned)((wn * 32 + g2 * 16) * 128) + boff
                                + (((unsigned)(ks * 32) + bcolb) ^ axor);
                ldsm4(bf[g2 * 2][0], bf[g2 * 2][1],
                      bf[g2 * 2 + 1][0], bf[g2 * 2 + 1][1], addr);
            }
            unsigned af[2][4];
#pragma unroll
            for (int mt = 0; mt < 2; mt++) {
                unsigned addr = sa + (unsigned)((wm * 32 + mt * 16) * 128) + aoff
                                + (((unsigned)(ks * 32) + acolb) ^ axor);
                ldsm4(af[mt][0], af[mt][1], af[mt][2], af[mt][3], addr);
            }
#pragma unroll
            for (int mt = 0; mt < 2; mt++)
#pragma unroll
                for (int nf = 0; nf < 4; nf++)
                    MMA_F16(acc[mt][nf], af[mt], bf[nf]);
        }
    }
    __syncthreads();   // all mma done before sRedF aliases smem

    // ---- epilogue pass 1: s = ee - acc/4096 in place + per-row mins ----
    float* sRedF = (float*)sm;                    // [4][128]
    float* sThr  = (float*)(sm + 2048);           // [128]

#pragma unroll
    for (int mt = 0; mt < 2; mt++) {
        float mn[2] = { __int_as_float(0x7f800000), __int_as_float(0x7f800000) };
#pragma unroll
        for (int nf = 0; nf < 4; nf++) {
#pragma unroll
            for (int r = 0; r < 4; r++) {
                const int n = nblk * NT + wn * 32 + nf * 8 + (lane & 3) * 2 + (r & 1);
                float s = fmaf(-INV4096, acc[mt][nf][r], __ldg(&g_ee[n]));
                acc[mt][nf][r] = s;
                mn[r >> 1] = fminf(mn[r >> 1], s);
            }
        }
#pragma unroll
        for (int rh = 0; rh < 2; rh++) {
            float v = mn[rh];
#pragma unroll
            for (int o = 1; o <= 2; o <<= 1)
                v = fminf(v, __shfl_xor_sync(0xffffffffu, v, o));
            if ((lane & 3) == 0)
                sRedF[wn * 128 + wm * 32 + mt * 16 + (lane >> 2) + rh * 8] = v;
        }
    }
    __syncthreads();
    if (tid < 128) {
        float mn = sRedF[tid];
#pragma unroll
        for (int w = 1; w < 4; w++) mn = fminf(mn, sRedF[w * 128 + tid]);
        const int rowg = mblk * MT + tid;
        atomicMin(&g_amin[rowg], msk(mn));
        sThr[tid] = mn + 2.0f * g_eps[rowg];
    }
    __syncthreads();

    // ---- epilogue pass 2: push from regs ----
#pragma unroll
    for (int mt = 0; mt < 2; mt++) {
#pragma unroll
        for (int rh = 0; rh < 2; rh++) {
            const int mloc = wm * 32 + mt * 16 + (lane >> 2) + rh * 8;
            const float thr = sThr[mloc];
            const int rowg = mblk * MT + mloc;
#pragma unroll
            for (int nf = 0; nf < 4; nf++) {
#pragma unroll
                for (int q = 0; q < 2; q++) {
                    float s = acc[mt][nf][rh * 2 + q];
                    if (s <= thr) {
                        const int n = nblk * NT + wn * 32 + nf * 8 + (lane & 3) * 2 + q;
                        unsigned idx = atomicAdd(&g_cnt[rowg], 1u);
                        if (idx < CAP)
                            g_cand[(size_t)rowg * CAP + idx] =
                                ((unsigned long long)msk(s) << 32) | (unsigned)n;
                    }
                }
            }
        }
    }
}

// ---------------- resolve + output + idx (fused) ----------------
__global__ void __launch_bounds__(256)
vq_resolve_kernel(const float* __restrict__ cb, const float* __restrict__ m,
                  float* __restrict__ out) {
    const int row  = blockIdx.x * 8 + (threadIdx.x >> 5);
    const int lane = threadIdx.x & 31;

    const unsigned rawcnt = g_cnt[row];
    const bool ovf = rawcnt > CAP;
    const int cnt = ovf ? CAP : (int)rawcnt;
    const float aminv = msk_inv(g_amin[row]);
    const unsigned thr = msk(aminv + 2.0f * g_eps[row]);

    float zreg[16];
    {
        const float4* zp = (const float4*)(g_zt + (size_t)row * C_DIM + lane * 16);
#pragma unroll
        for (int q = 0; q < 4; q++) {
            float4 v = zp[q];
            zreg[q * 4 + 0] = v.x; zreg[q * 4 + 1] = v.y;
            zreg[q * 4 + 2] = v.z; zreg[q * 4 + 3] = v.w;
        }
    }
    const float zz = g_zz[row];
    unsigned long long best = ~0ull;

    auto exact_eval = [&](int j) {
        const float4* cp = (const float4*)(cb + (size_t)j * C_DIM + lane * 16);
        float d = 0.0f;
#pragma unroll
        for (int q = 0; q < 4; q++) {
            float4 cv = __ldg(cp + q);
            d = fmaf(zreg[q * 4 + 0], cv.x, d);
            d = fmaf(zreg[q * 4 + 1], cv.y, d);
            d = fmaf(zreg[q * 4 + 2], cv.z, d);
            d = fmaf(zreg[q * 4 + 3], cv.w, d);
        }
#pragma unroll
        for (int o = 16; o; o >>= 1) d += __shfl_xor_sync(0xffffffffu, d, o);
        float ve = __fsub_rn(__fadd_rn(zz, __ldg(&g_ee[j])), 2.0f * d);
        unsigned long long pv =
            ((unsigned long long)__float_as_uint(ve) << 32) | (unsigned)j;
        if (pv < best) best = pv;
    };

    if (!ovf) {
        const unsigned long long* cl = g_cand + (size_t)row * CAP;
        for (int i = 0; i < cnt; i++) {
            unsigned long long e = cl[i];
            if ((unsigned)(e >> 32) <= thr)
                exact_eval((int)(e & 0xffffffffu));
        }
    } else {
        for (int j = 0; j < NE; j++) exact_eval(j);
    }

    const int j = (int)(best & 0xffffffffu);
    const float4* cq = (const float4*)(cb + (size_t)j * C_DIM + lane * 16);
    float4* op = (float4*)(out + (size_t)row * C_DIM + lane * 16);
    float ssq = 0.0f;
#pragma unroll
    for (int q = 0; q < 4; q++) {
        float4 cv = __ldg(cq + q);
        float4 o;
        float t;
        t = cv.x - zreg[q * 4 + 0]; ssq = fmaf(t, t, ssq); o.x = zreg[q * 4 + 0] + t;
        t = cv.y - zreg[q * 4 + 1]; ssq = fmaf(t, t, ssq); o.y = zreg[q * 4 + 1] + t;
        t = cv.z - zreg[q * 4 + 2]; ssq = fmaf(t, t, ssq); o.z = zreg[q * 4 + 2] + t;
        t = cv.w - zreg[q * 4 + 3]; ssq = fmaf(t, t, ssq); o.w = zreg[q * 4 + 3] + t;
        op[q] = o;
    }
#pragma unroll
    for (int o = 16; o; o >>= 1) ssq += __shfl_xor_sync(0xffffffffu, ssq, o);
    if (lane == 0) {
        if (m[row] == 0.0f) atomicAdd(&g_sumsq, ssq);
        out[(size_t)N_ROWS * C_DIM + 1 + row] = (float)j;
    }
}

// ---------------- scalar loss (deterministic wpart sum) --------------
__global__ void vq_finalize_kernel(float* __restrict__ out) {
    int lane = threadIdx.x & 31;
    float w = 0.0f;
#pragma unroll
    for (int i = 0; i < 4; i++) w += g_wpart[lane + 32 * i];
#pragma unroll
    for (int o = 16; o; o >>= 1) w += __shfl_xor_sync(0xffffffffu, w, o);
    if (lane == 0)
        out[(size_t)N_ROWS * C_DIM] = (1.0f + BETA_F) * g_sumsq / (w * (float)C_DIM);
}

// ---------------- launch ----------------
extern "C" void kernel_launch(void* const* d_in, const int* in_sizes, int n_in,
                              void* d_out, int out_size) {
    (void)in_sizes; (void)n_in; (void)out_size;
    const float* z  = (const float*)d_in[0];
    const float* m  = (const float*)d_in[1];
    const float* cb = (const float*)d_in[2];
    float* out = (float*)d_out;

    cudaFuncSetAttribute(vq_mma_kernel,
                         cudaFuncAttributeMaxDynamicSharedMemorySize, SMEM_TOTAL);

    vq_prep_kernel<<<N_ROWS / 256, 256>>>(z, m);
    vq_cb_kernel<<<NE * 32 / 256, 256>>>(cb);
    vq_zsplit_kernel<<<4096, 256>>>(z);
    vq_mma_kernel<<<MBLK * NBLK, 512, SMEM_TOTAL>>>();
    vq_resolve_kernel<<<N_ROWS / 8, 256>>>(cb, m, out);
    vq_finalize_kernel<<<1, 32>>>(out);
}

// round 17
// speedup vs baseline: 1.9687x; 1.0643x over previous
#include <cuda_runtime.h>
#include <cuda_fp16.h>

#define N_ROWS 32768
#define C_DIM  512
#define NE     8192
#define HW     4096
#define BETA_F 0.25f

// GEMM tiling: CTA 128x128 (512 threads), warp 32x32, KC=64
#define MT 128
#define NT 128
#define KC 64
#define NCHUNK (C_DIM / KC)     // 8
#define NBLK   (NE / NT)        // 64
#define MBLK   (N_ROWS / MT)    // 256

#define STAGE_BYTES 32768u
#define TILE_BYTES  16384u
#define SMEM_TOTAL  98304       // 3 stages

#define CAP 512
#define INV4096 2.44140625e-4f  // 2^-12, exact

// ---------------- device scratch ----------------
__device__ float g_zz[N_ROWS];
__device__ float g_eps[N_ROWS];
__device__ float g_ee[NE];
__device__ float g_zzp[8 * N_ROWS];      // per-c0-block partial sum z^2
__device__ float g_sap[8 * N_ROWS];      // per-c0-block partial sum |z|
__device__ unsigned g_amin[N_ROWS];
__device__ unsigned g_cnt[N_ROWS];
__device__ unsigned long long g_cand[(size_t)N_ROWS * CAP];
__device__ float g_wpart[N_ROWS / 256];
__device__ float g_sumsq;
__device__ __half g_Ah[(size_t)N_ROWS * C_DIM];
__device__ __half g_Bh[(size_t)NE * C_DIM];          // codebook * 2^13
__device__ float g_zt[(size_t)N_ROWS * C_DIM];

// ---------------- helpers ----------------
__device__ __forceinline__ void cpa16(unsigned dst, const void* src) {
    asm volatile("cp.async.cg.shared.global [%0], [%1], 16;" :: "r"(dst), "l"(src));
}
__device__ __forceinline__ void ldsm4(unsigned &r0, unsigned &r1, unsigned &r2,
                                      unsigned &r3, unsigned addr) {
    asm volatile("ldmatrix.sync.aligned.m8n8.x4.shared.b16 {%0,%1,%2,%3},[%4];"
                 : "=r"(r0), "=r"(r1), "=r"(r2), "=r"(r3) : "r"(addr));
}
#define MMA_F16(d, a, b) \
    asm volatile("mma.sync.aligned.m16n8k16.row.col.f32.f16.f16.f32 " \
        "{%0,%1,%2,%3},{%4,%5,%6,%7},{%8,%9},{%0,%1,%2,%3};" \
        : "+f"((d)[0]), "+f"((d)[1]), "+f"((d)[2]), "+f"((d)[3]) \
        : "r"((a)[0]), "r"((a)[1]), "r"((a)[2]), "r"((a)[3]), \
          "r"((b)[0]), "r"((b)[1]))

__device__ __forceinline__ unsigned msk(float s) {
    unsigned b = __float_as_uint(s);
    return b ^ ((b & 0x80000000u) ? 0xFFFFFFFFu : 0x80000000u);
}
__device__ __forceinline__ float msk_inv(unsigned v) {
    return (v & 0x80000000u) ? __uint_as_float(v ^ 0x80000000u)
                             : __uint_as_float(~v);
}

// ---------------- z: NCHW -> [N,C] + deterministic row partials ----------
__global__ void vq_zsplit_kernel(const float* __restrict__ z) {
    __shared__ float t[64][65];
    __shared__ float psq[4][64];
    __shared__ float pab[4][64];
    int bid = blockIdx.x;
    int hw0   = (bid & 63) * 64;
    int c0blk = (bid >> 6) & 7;
    int c0    = c0blk * 64;
    int b     = bid >> 9;
    int tid = threadIdx.x;
    int q = tid >> 6;
    int l = tid & 63;
    const float* zp = z + ((size_t)b * C_DIM + c0) * HW + hw0;
#pragma unroll
    for (int s = 0; s < 16; s++) {
        int c = s * 4 + q;
        t[c][l] = zp[(size_t)c * HW + l];
    }
    __syncthreads();
    size_t rowbase = (size_t)b * HW + hw0;
#pragma unroll
    for (int s = 0; s < 16; s++) {
        int n = s * 4 + q;
        float a = t[l][n];
        size_t o = (rowbase + n) * C_DIM + c0 + l;
        g_zt[o] = a;
        g_Ah[o] = __float2half_rn(a);
    }
    // partials: thread (q,l) -> row hw0+l, channels [c0+16q, c0+16q+16)
    {
        float sq = 0.0f, sa = 0.0f;
#pragma unroll
        for (int i = 0; i < 16; i++) {
            float v = t[q * 16 + i][l];
            sq = fmaf(v, v, sq);
            sa += fabsf(v);
        }
        psq[q][l] = sq;
        pab[q][l] = sa;
    }
    __syncthreads();
    if (tid < 64) {
        float s  = ((psq[0][tid] + psq[1][tid]) + psq[2][tid]) + psq[3][tid];
        float sa = ((pab[0][tid] + pab[1][tid]) + pab[2][tid]) + pab[3][tid];
        g_zzp[c0blk * N_ROWS + (int)rowbase + tid] = s;
        g_sap[c0blk * N_ROWS + (int)rowbase + tid] = sa;
    }
}

// ---------------- prep2 (fused): zz/eps/init from partials + cb convert --
__global__ void vq_prep2_kernel(const float* __restrict__ m,
                                const float* __restrict__ cb) {
    if (blockIdx.x < N_ROWS / 256) {
        __shared__ float wred[8];
        int n = blockIdx.x * 256 + threadIdx.x;
        float s = 0.0f, sa = 0.0f;
#pragma unroll
        for (int k = 0; k < 8; k++) {      // fixed order: deterministic
            s  += g_zzp[k * N_ROWS + n];
            sa += g_sap[k * N_ROWS + n];
        }
        g_zz[n] = s;
        g_eps[n] = fmaf(2.5e-7f, sa, 1.5e-4f);   // validated fp16-probe bound
        g_amin[n] = 0xFFFFFFFFu;
        g_cnt[n] = 0u;
        if (n == 0) g_sumsq = 0.0f;

        float w = (m[n] == 0.0f) ? 1.0f : 0.0f;  // integer-valued: order-exact
#pragma unroll
        for (int o = 16; o; o >>= 1) w += __shfl_xor_sync(0xffffffffu, w, o);
        if ((threadIdx.x & 31) == 0) wred[threadIdx.x >> 5] = w;
        __syncthreads();
        if (threadIdx.x == 0) {
            float t = 0.0f;
#pragma unroll
            for (int i = 0; i < 8; i++) t += wred[i];
            g_wpart[blockIdx.x] = t;
        }
    } else {
        // cb: ee[j] + fp16*2^13 conversion (one pass over the codebook)
        int bj   = blockIdx.x - N_ROWS / 256;
        int j    = (bj * 256 + threadIdx.x) >> 5;
        int lane = threadIdx.x & 31;
        const float4* p = (const float4*)(cb + (size_t)j * C_DIM);
        __half* hp = g_Bh + (size_t)j * C_DIM;
        float s = 0.0f;
#pragma unroll
        for (int i = 0; i < 4; i++) {
            float4 v = p[lane + 32 * i];
            s = fmaf(v.x, v.x, fmaf(v.y, v.y, fmaf(v.z, v.z, fmaf(v.w, v.w, s))));
            __half2* hq = (__half2*)(hp + (lane + 32 * i) * 4);
            hq[0] = __floats2half2_rn(v.x * 8192.0f, v.y * 8192.0f);
            hq[1] = __floats2half2_rn(v.z * 8192.0f, v.w * 8192.0f);
        }
#pragma unroll
        for (int o = 16; o; o >>= 1) s += __shfl_xor_sync(0xffffffffu, s, o);
        if (lane == 0) g_ee[j] = s;
    }
}

// ---------------- fp16 HMMA GEMM (512thr, single-sync loop) --------------
__global__ void __launch_bounds__(512, 2)
vq_mma_kernel() {
    extern __shared__ __align__(128) char sm[];
    const unsigned smb = (unsigned)__cvta_generic_to_shared(sm);

    const int tid  = threadIdx.x;
    const int lane = tid & 31;
    const int wid  = tid >> 5;        // 0..15
    const int wm   = wid >> 2;        // 0..3 (32 rows each)
    const int wn   = wid & 3;         // 0..3 (32 cols each)
    const int mblk = blockIdx.x >> 6;
    const int nblk = blockIdx.x & 63;

    const __half* Ahg = g_Ah + (size_t)(mblk * MT) * C_DIM;
    const __half* Bhg = g_Bh + (size_t)(nblk * NT) * C_DIM;

    const unsigned axor  = (unsigned)(lane & 7) << 4;
    const unsigned aoff  = (unsigned)(((lane & 7) + ((lane >> 3) & 1) * 8) * 128);
    const unsigned acolb = (unsigned)(((lane >> 4) & 1) * 16);
    const unsigned boff  = (unsigned)(((lane & 7) + ((lane >> 4) & 1) * 8) * 128);
    const unsigned bcolb = (unsigned)(((lane >> 3) & 1) * 16);

    float acc[2][4][4];
#pragma unroll
    for (int mt = 0; mt < 2; mt++)
#pragma unroll
        for (int nf = 0; nf < 4; nf++)
#pragma unroll
            for (int r = 0; r < 4; r++) acc[mt][nf][r] = 0.0f;

    auto load_stage = [&](int st, int k0) {
        const unsigned sb0 = smb + (unsigned)st * STAGE_BYTES;
#pragma unroll
        for (int i = 0; i < 2; i++) {
            int g = tid + 512 * i;
            int row = g >> 3;
            int c = g & 7;
            unsigned off = (unsigned)(row * 128) +
                           (((unsigned)(c * 16)) ^ ((unsigned)(row & 7) << 4));
            const size_t so = (size_t)row * C_DIM + k0 + c * 8;
            cpa16(sb0 + off, Ahg + so);
            cpa16(sb0 + TILE_BYTES + off, Bhg + so);
        }
        asm volatile("cp.async.commit_group;" ::: "memory");
    };

    load_stage(0, 0);
    load_stage(1, 1 * KC);

    for (int c = 0; c < NCHUNK; c++) {
        const int st = c % 3;
        if (c + 1 < NCHUNK) {
            asm volatile("cp.async.wait_group 1;" ::: "memory");
        } else {
            asm volatile("cp.async.wait_group 0;" ::: "memory");
        }
        __syncthreads();
        if (c + 2 < NCHUNK)
            load_stage((c + 2) % 3, (c + 2) * KC);

        const unsigned sa = smb + (unsigned)st * STAGE_BYTES;
        const unsigned sb = sa + TILE_BYTES;
#pragma unroll
        for (int ks = 0; ks < 4; ks++) {
            unsigned bf[4][2];
#pragma unroll
            for (int g2 = 0; g2 < 2; g2++) {
                unsigned addr = sb + (unsigned)((wn * 32 + g2 * 16) * 128) + boff
                                + (((unsigned)(ks * 32) + bcolb) ^ axor);
                ldsm4(bf[g2 * 2][0], bf[g2 * 2][1],
                      bf[g2 * 2 + 1][0], bf[g2 * 2 + 1][1], addr);
            }
            unsigned af[2][4];
#pragma unroll
            for (int mt = 0; mt < 2; mt++) {
                unsigned addr = sa + (unsigned)((wm * 32 + mt * 16) * 128) + aoff
                                + (((unsigned)(ks * 32) + acolb) ^ axor);
                ldsm4(af[mt][0], af[mt][1], af[mt][2], af[mt][3], addr);
            }
#pragma unroll
            for (int mt = 0; mt < 2; mt++)
#pragma unroll
                for (int nf = 0; nf < 4; nf++)
                    MMA_F16(acc[mt][nf], af[mt], bf[nf]);
        }
    }
    __syncthreads();   // all mma done before sRedF aliases smem

    // ---- epilogue pass 1: s = ee - acc/4096 in place + per-row mins ----
    float* sRedF = (float*)sm;                    // [4][128]
    float* sThr  = (float*)(sm + 2048);           // [128]

#pragma unroll
    for (int mt = 0; mt < 2; mt++) {
        float mn[2] = { __int_as_float(0x7f800000), __int_as_float(0x7f800000) };
#pragma unroll
        for (int nf = 0; nf < 4; nf++) {
#pragma unroll
            for (int r = 0; r < 4; r++) {
                const int n = nblk * NT + wn * 32 + nf * 8 + (lane & 3) * 2 + (r & 1);
                float s = fmaf(-INV4096, acc[mt][nf][r], __ldg(&g_ee[n]));
                acc[mt][nf][r] = s;
                mn[r >> 1] = fminf(mn[r >> 1], s);
            }
        }
#pragma unroll
        for (int rh = 0; rh < 2; rh++) {
            float v = mn[rh];
#pragma unroll
            for (int o = 1; o <= 2; o <<= 1)
                v = fminf(v, __shfl_xor_sync(0xffffffffu, v, o));
            if ((lane & 3) == 0)
                sRedF[wn * 128 + wm * 32 + mt * 16 + (lane >> 2) + rh * 8] = v;
        }
    }
    __syncthreads();
    if (tid < 128) {
        float mn = sRedF[tid];
#pragma unroll
        for (int w = 1; w < 4; w++) mn = fminf(mn, sRedF[w * 128 + tid]);
        const int rowg = mblk * MT + tid;
        atomicMin(&g_amin[rowg], msk(mn));
        sThr[tid] = mn + 2.0f * g_eps[rowg];
    }
    __syncthreads();

    // ---- epilogue pass 2: push from regs ----
#pragma unroll
    for (int mt = 0; mt < 2; mt++) {
#pragma unroll
        for (int rh = 0; rh < 2; rh++) {
            const int mloc = wm * 32 + mt * 16 + (lane >> 2) + rh * 8;
            const float thr = sThr[mloc];
            const int rowg = mblk * MT + mloc;
#pragma unroll
            for (int nf = 0; nf < 4; nf++) {
#pragma unroll
                for (int q = 0; q < 2; q++) {
                    float s = acc[mt][nf][rh * 2 + q];
                    if (s <= thr) {
                        const int n = nblk * NT + wn * 32 + nf * 8 + (lane & 3) * 2 + q;
                        unsigned idx = atomicAdd(&g_cnt[rowg], 1u);
                        if (idx < CAP)
                            g_cand[(size_t)rowg * CAP + idx] =
                                ((unsigned long long)msk(s) << 32) | (unsigned)n;
                    }
                }
            }
        }
    }
}

// ---------------- resolve + output + idx (fused) ----------------
__global__ void __launch_bounds__(256)
vq_resolve_kernel(const float* __restrict__ cb, const float* __restrict__ m,
                  float* __restrict__ out) {
    const int row  = blockIdx.x * 8 + (threadIdx.x >> 5);
    const int lane = threadIdx.x & 31;

    const unsigned rawcnt = g_cnt[row];
    const bool ovf = rawcnt > CAP;
    const int cnt = ovf ? CAP : (int)rawcnt;
    const float aminv = msk_inv(g_amin[row]);
    const unsigned thr = msk(aminv + 2.0f * g_eps[row]);

    float zreg[16];
    {
        const float4* zp = (const float4*)(g_zt + (size_t)row * C_DIM + lane * 16);
#pragma unroll
        for (int q = 0; q < 4; q++) {
            float4 v = zp[q];
            zreg[q * 4 + 0] = v.x; zreg[q * 4 + 1] = v.y;
            zreg[q * 4 + 2] = v.z; zreg[q * 4 + 3] = v.w;
        }
    }
    const float zz = g_zz[row];
    unsigned long long best = ~0ull;

    auto exact_eval = [&](int j) {
        const float4* cp = (const float4*)(cb + (size_t)j * C_DIM + lane * 16);
        float d = 0.0f;
#pragma unroll
        for (int q = 0; q < 4; q++) {
            float4 cv = __ldg(cp + q);
            d = fmaf(zreg[q * 4 + 0], cv.x, d);
            d = fmaf(zreg[q * 4 + 1], cv.y, d);
            d = fmaf(zreg[q * 4 + 2], cv.z, d);
            d = fmaf(zreg[q * 4 + 3], cv.w, d);
        }
#pragma unroll
        for (int o = 16; o; o >>= 1) d += __shfl_xor_sync(0xffffffffu, d, o);
        float ve = __fsub_rn(__fadd_rn(zz, __ldg(&g_ee[j])), 2.0f * d);
        unsigned long long pv =
            ((unsigned long long)__float_as_uint(ve) << 32) | (unsigned)j;
        if (pv < best) best = pv;
    };

    if (!ovf) {
        const unsigned long long* cl = g_cand + (size_t)row * CAP;
        for (int i = 0; i < cnt; i++) {
            unsigned long long e = cl[i];
            if ((unsigned)(e >> 32) <= thr)
                exact_eval((int)(e & 0xffffffffu));
        }
    } else {
        for (int j = 0; j < NE; j++) exact_eval(j);
    }

    const int j = (int)(best & 0xffffffffu);
    const float4* cq = (const float4*)(cb + (size_t)j * C_DIM + lane * 16);
    float4* op = (float4*)(out + (size_t)row * C_DIM + lane * 16);
    float ssq = 0.0f;
#pragma unroll
    for (int q = 0; q < 4; q++) {
        float4 cv = __ldg(cq + q);
        float4 o;
        float t;
        t = cv.x - zreg[q * 4 + 0]; ssq = fmaf(t, t, ssq); o.x = zreg[q * 4 + 0] + t;
        t = cv.y - zreg[q * 4 + 1]; ssq = fmaf(t, t, ssq); o.y = zreg[q * 4 + 1] + t;
        t = cv.z - zreg[q * 4 + 2]; ssq = fmaf(t, t, ssq); o.z = zreg[q * 4 + 2] + t;
        t = cv.w - zreg[q * 4 + 3]; ssq = fmaf(t, t, ssq); o.w = zreg[q * 4 + 3] + t;
        op[q] = o;
    }
#pragma unroll
    for (int o = 16; o; o >>= 1) ssq += __shfl_xor_sync(0xffffffffu, ssq, o);
    if (lane == 0) {
        if (m[row] == 0.0f) atomicAdd(&g_sumsq, ssq);
        out[(size_t)N_ROWS * C_DIM + 1 + row] = (float)j;
    }
}

// ---------------- scalar loss (deterministic wpart sum) --------------
__global__ void vq_finalize_kernel(float* __restrict__ out) {
    int lane = threadIdx.x & 31;
    float w = 0.0f;
#pragma unroll
    for (int i = 0; i < 4; i++) w += g_wpart[lane + 32 * i];
#pragma unroll
    for (int o = 16; o; o >>= 1) w += __shfl_xor_sync(0xffffffffu, w, o);
    if (lane == 0)
        out[(size_t)N_ROWS * C_DIM] = (1.0f + BETA_F) * g_sumsq / (w * (float)C_DIM);
}

// ---------------- launch ----------------
extern "C" void kernel_launch(void* const* d_in, const int* in_sizes, int n_in,
                              void* d_out, int out_size) {
    (void)in_sizes; (void)n_in; (void)out_size;
    const float* z  = (const float*)d_in[0];
    const float* m  = (const float*)d_in[1];
    const float* cb = (const float*)d_in[2];
    float* out = (float*)d_out;

    cudaFuncSetAttribute(vq_mma_kernel,
                         cudaFuncAttributeMaxDynamicSharedMemorySize, SMEM_TOTAL);

    vq_zsplit_kernel<<<4096, 256>>>(z);
    vq_prep2_kernel<<<N_ROWS / 256 + NE * 32 / 256, 256>>>(m, cb);
    vq_mma_kernel<<<MBLK * NBLK, 512, SMEM_TOTAL>>>();
    vq_resolve_kernel<<<N_ROWS / 8, 256>>>(cb, m, out);
    vq_finalize_kernel<<<1, 32>>>(out);
}